// round 1
// baseline (speedup 1.0000x reference)
#include <cuda_runtime.h>

// LSTM: HIDDEN=51, INPUT=1, BATCH=4096, SEQ=999, future=0.
// Strategy: 4 threads per batch element, 13 hidden units per thread (padded to 52
// with an inert dummy unit). W_hh in SMEM (52-float rows, conflict-free for the
// 4-distinct-address LDS.128 pattern). h/c state per element in SMEM; the 4 owner
// threads live in one quad of a warp -> __syncwarp only, no block barriers in the
// 999-step loop. Gate dot-products via packed fma.rn.f32x2 (Blackwell f32x2 pipe).

#define HIDDEN   51
#define HP       52      // padded hidden
#define SEQN     999
#define BATCHN   4096
#define ROWW     52      // weight row stride (floats)
#define UPT      13      // units per thread
#define EPB      32      // batch elements per block
#define NTHREADS 128

typedef unsigned long long u64;

__device__ __forceinline__ u64 pack2(float lo, float hi) {
    u64 r; asm("mov.b64 %0, {%1, %2};" : "=l"(r) : "f"(lo), "f"(hi)); return r;
}
__device__ __forceinline__ float2 unpack2(u64 p) {
    float2 r; asm("mov.b64 {%0, %1}, %2;" : "=f"(r.x), "=f"(r.y) : "l"(p)); return r;
}
// Packed fp32 FMA: d = a*b + d elementwise on 2 floats (Blackwell f32x2 pipe).
__device__ __forceinline__ u64 ffma2(u64 a, u64 b, u64 d) {
    asm("fma.rn.f32x2 %0, %1, %2, %0;" : "+l"(d) : "l"(a), "l"(b)); return d;
}
// Accurate-enough sigmoid/tanh: ex2.approx (~2^-22 rel) + rcp.approx (~2^-23).
__device__ __forceinline__ float fsig(float x) {
    float e; asm("ex2.approx.ftz.f32 %0, %1;" : "=f"(e) : "f"(-1.4426950408889634f * x));
    float r; asm("rcp.approx.ftz.f32 %0, %1;" : "=f"(r) : "f"(1.0f + e));
    return r;
}
__device__ __forceinline__ float ftanh(float x) {
    return fmaf(2.0f, fsig(2.0f * x), -1.0f);
}

__global__ void __launch_bounds__(NTHREADS, 1) lstm_kernel(
    const float* __restrict__ input,  // (B, T, 1)
    const float* __restrict__ W_ih,   // (4H, 1)
    const float* __restrict__ W_hh,   // (4H, H)
    const float* __restrict__ b_ih,   // (4H,)
    const float* __restrict__ b_hh,   // (4H,)
    const float* __restrict__ W_fc,   // (1, H)
    const float* __restrict__ b_fc,   // (1,)
    float* __restrict__ out)          // (B, T, 1)
{
    extern __shared__ float sm[];
    float* Wsh  = sm;                       // 4 * HP * ROWW = 10816 floats
    float* preb = Wsh + 4 * HP * ROWW;      // 4 * HP  (b_ih + b_hh, padded)
    float* wih  = preb + 4 * HP;            // 4 * HP
    float* wfc  = wih + 4 * HP;             // HP
    float* hsh  = wfc + HP;                 // EPB * HP
    float* csh  = hsh + EPB * HP;           // EPB * HP

    const int tid = threadIdx.x;

    // Stage weights (gate g, unit u, k) -> Wsh[(g*HP+u)*ROWW + k], zero-padded.
    for (int idx = tid; idx < 4 * HP * ROWW; idx += NTHREADS) {
        int row = idx / ROWW, k = idx - row * ROWW;
        int g = row / HP, u = row - g * HP;
        Wsh[idx] = (u < HIDDEN && k < HIDDEN) ? W_hh[(g * HIDDEN + u) * HIDDEN + k] : 0.0f;
    }
    for (int idx = tid; idx < 4 * HP; idx += NTHREADS) {
        int g = idx / HP, u = idx - g * HP;
        float bb = 0.0f, wv = 0.0f;
        if (u < HIDDEN) {
            bb = b_ih[g * HIDDEN + u] + b_hh[g * HIDDEN + u];
            wv = W_ih[g * HIDDEN + u];
        }
        preb[idx] = bb; wih[idx] = wv;
    }
    for (int idx = tid; idx < HP; idx += NTHREADS)
        wfc[idx] = (idx < HIDDEN) ? W_fc[idx] : 0.0f;
    for (int idx = tid; idx < 2 * EPB * HP; idx += NTHREADS)
        hsh[idx] = 0.0f;   // zeros hsh and csh (contiguous)
    __syncthreads();

    // lane = e_local*4 + s : quad (4 lanes) owns one batch element.
    const int lane = tid & 31;
    const int s    = lane & 3;                      // sub-thread id (unit group)
    const int e    = ((tid >> 5) << 3) + (lane >> 2); // element in block, 0..31
    const int b    = blockIdx.x * EPB + e;
    const int u0   = s * UPT;

    const float* xin  = input + (size_t)b * SEQN;
    float* hrow = hsh + e * HP;
    float* crow = csh + e * HP;
    float* outp = out + (size_t)b * SEQN;
    const float bfc = b_fc[0];

    float x = __ldg(xin);
    for (int t = 0; t < SEQN; t++) {
        // Prefetch next timestep's input so the global load hides under compute.
        int tn = (t + 1 < SEQN) ? t + 1 : SEQN - 1;
        float xnext = __ldg(xin + tn);

        // Snapshot h into registers as packed f32x2 pairs.
        u64 h2[26];
        #pragma unroll
        for (int i = 0; i < 13; i++) {
            float4 v = ((const float4*)hrow)[i];
            h2[2 * i]     = pack2(v.x, v.y);
            h2[2 * i + 1] = pack2(v.z, v.w);
        }
        __syncwarp();   // everyone snapshotted before anyone overwrites hrow

        float ypart = 0.0f;
        #pragma unroll 1
        for (int ul = 0; ul < UPT; ul++) {
            const int u = u0 + ul;
            const float* wr = Wsh + u * ROWW;
            u64 ai = 0, af = 0, ag = 0, ao = 0;
            #pragma unroll
            for (int c4 = 0; c4 < 13; c4++) {
                float4 wi4 = *(const float4*)(wr + 4 * c4);
                float4 wf4 = *(const float4*)(wr + HP * ROWW + 4 * c4);
                float4 wg4 = *(const float4*)(wr + 2 * HP * ROWW + 4 * c4);
                float4 wo4 = *(const float4*)(wr + 3 * HP * ROWW + 4 * c4);
                u64 hlo = h2[2 * c4], hhi = h2[2 * c4 + 1];
                ai = ffma2(pack2(wi4.x, wi4.y), hlo, ai);
                ai = ffma2(pack2(wi4.z, wi4.w), hhi, ai);
                af = ffma2(pack2(wf4.x, wf4.y), hlo, af);
                af = ffma2(pack2(wf4.z, wf4.w), hhi, af);
                ag = ffma2(pack2(wg4.x, wg4.y), hlo, ag);
                ag = ffma2(pack2(wg4.z, wg4.w), hhi, ag);
                ao = ffma2(pack2(wo4.x, wo4.y), hlo, ao);
                ao = ffma2(pack2(wo4.z, wo4.w), hhi, ao);
            }
            float2 vi = unpack2(ai), vf = unpack2(af), vg = unpack2(ag), vo = unpack2(ao);
            float gi = vi.x + vi.y + fmaf(wih[u],          x, preb[u]);
            float gf = vf.x + vf.y + fmaf(wih[HP + u],     x, preb[HP + u]);
            float gg = vg.x + vg.y + fmaf(wih[2 * HP + u], x, preb[2 * HP + u]);
            float go = vo.x + vo.y + fmaf(wih[3 * HP + u], x, preb[3 * HP + u]);

            float cn = fsig(gf) * crow[u] + fsig(gi) * ftanh(gg);
            crow[u] = cn;
            float hn = fsig(go) * ftanh(cn);
            hrow[u] = hn;                       // conflict-free STS (verified map)
            ypart = fmaf(hn, wfc[u], ypart);
        }
        __syncwarp();   // all h writes visible before next step's snapshot

        // Reduce y over the quad; sub-thread 0 writes the output.
        ypart += __shfl_xor_sync(0xffffffffu, ypart, 1);
        ypart += __shfl_xor_sync(0xffffffffu, ypart, 2);
        if (s == 0) outp[t] = ypart + bfc;

        x = xnext;
    }
}

extern "C" void kernel_launch(void* const* d_in, const int* in_sizes, int n_in,
                              void* d_out, int out_size)
{
    const float* input = (const float*)d_in[0];
    const float* W_ih  = (const float*)d_in[1];
    const float* W_hh  = (const float*)d_in[2];
    const float* b_ih  = (const float*)d_in[3];
    const float* b_hh  = (const float*)d_in[4];
    const float* W_fc  = (const float*)d_in[5];
    const float* b_fc  = (const float*)d_in[6];
    // d_in[7] = future (0) — statically known, ignored.
    float* out = (float*)d_out;

    const size_t smem = (size_t)(4 * HP * ROWW + 8 * HP + HP + 2 * EPB * HP) * sizeof(float);
    cudaFuncSetAttribute(lstm_kernel, cudaFuncAttributeMaxDynamicSharedMemorySize, (int)smem);
    lstm_kernel<<<BATCHN / EPB, NTHREADS, smem>>>(input, W_ih, W_hh, b_ih, b_hh,
                                                  W_fc, b_fc, out);
}

// round 9
// speedup vs baseline: 1.3778x; 1.3778x over previous
#include <cuda_runtime.h>

// LSTM: HIDDEN=51, INPUT=1, BATCH=4096, SEQ=999, future=0.
//
// Layout: element-per-lane, gate-per-warp.
//   256 threads = 8 warps; 32 batch elements per CTA (element == lane id).
//   Warp w: gate g = w&3 (i,f,g,o), unit half uh = w>>2 (units uh*26..uh*26+25).
//   Weight rows live in SMEM; every weight LDS.128 is warp-uniform broadcast
//   (1 L1 wavefront) — this removes the L1 bottleneck of the R1 kernel.
//   h (52 pad) is register-resident per lane as packed f32x2; x and bias are
//   folded into weight-row k-slots 52 (x) and 53 (1.0*bias).
//   Gates go through SMEM; 2 __syncthreads per timestep.

#define HIDDEN  51
#define UP      52          // padded units (unit 51 is inert dummy)
#define KP      56          // padded row length: k 0..50 = W_hh, 52 = W_ih, 53 = bias
#define SEQN    999
#define BATCHN  4096
#define EPB     32          // elements per CTA (= lanes)
#define NTHREADS 256

typedef unsigned long long u64;

__device__ __forceinline__ u64 pack2(float lo, float hi) {
    u64 r; asm("mov.b64 %0, {%1, %2};" : "=l"(r) : "f"(lo), "f"(hi)); return r;
}
__device__ __forceinline__ float2 unpack2(u64 p) {
    float2 r; asm("mov.b64 {%0, %1}, %2;" : "=f"(r.x), "=f"(r.y) : "l"(p)); return r;
}
__device__ __forceinline__ u64 ffma2(u64 a, u64 b, u64 d) {
    asm("fma.rn.f32x2 %0, %1, %2, %0;" : "+l"(d) : "l"(a), "l"(b)); return d;
}
// sigmoid/tanh via ex2+rcp (proven rel_err 2e-7 in R1)
__device__ __forceinline__ float fsig(float x) {
    float e; asm("ex2.approx.ftz.f32 %0, %1;" : "=f"(e) : "f"(-1.4426950408889634f * x));
    float r; asm("rcp.approx.ftz.f32 %0, %1;" : "=f"(r) : "f"(1.0f + e));
    return r;
}
__device__ __forceinline__ float ftanh(float x) {
    return fmaf(2.0f, fsig(2.0f * x), -1.0f);
}

// SMEM plan (floats):
//   Wsh : 4*UP rows x KP           = 208*56 = 11648
//   gsh : 4*UP rows x EPB (gates)  = 208*32 =  6656
//   hsh : EPB x 54 (h exchange)    =  32*54 =  1728
//   wfc : KP                        =            56
#define WSH_F   (4 * UP * KP)
#define GSH_F   (4 * UP * EPB)
#define HSTRIDE 54
#define HSH_F   (EPB * HSTRIDE)
#define SMEM_F  (WSH_F + GSH_F + HSH_F + KP)

__global__ void __launch_bounds__(NTHREADS, 1) lstm_kernel(
    const float* __restrict__ input,  // (B, T, 1)
    const float* __restrict__ W_ih,   // (4H, 1)
    const float* __restrict__ W_hh,   // (4H, H)
    const float* __restrict__ b_ih,   // (4H,)
    const float* __restrict__ b_hh,   // (4H,)
    const float* __restrict__ W_fc,   // (1, H)
    const float* __restrict__ b_fc,   // (1,)
    float* __restrict__ out)          // (B, T, 1)
{
    extern __shared__ float sm[];
    float* Wsh  = sm;
    float* gsh  = Wsh + WSH_F;
    float* hsh  = gsh + GSH_F;
    float* wfcs = hsh + HSH_F;

    const int tid  = threadIdx.x;
    const int wid  = tid >> 5;
    const int lane = tid & 31;

    // ---- stage weights ----
    // Row r = g*UP + u (u<51 real). k<51: W_hh; k==52: W_ih; k==53: b_ih+b_hh; else 0.
    for (int idx = tid; idx < WSH_F; idx += NTHREADS) {
        int r = idx / KP, k = idx - r * KP;
        int g = r / UP, u = r - g * UP;
        float v = 0.0f;
        if (u < HIDDEN) {
            int rr = g * HIDDEN + u;
            if (k < HIDDEN)      v = W_hh[rr * HIDDEN + k];
            else if (k == 52)    v = W_ih[rr];
            else if (k == 53)    v = b_ih[rr] + b_hh[rr];
        }
        Wsh[idx] = v;
    }
    for (int idx = tid; idx < KP; idx += NTHREADS)
        wfcs[idx] = (idx < HIDDEN) ? W_fc[idx] : 0.0f;
    for (int idx = tid; idx < HSH_F; idx += NTHREADS)
        hsh[idx] = 0.0f;
    __syncthreads();

    const int g  = wid & 3;          // gate owned by this warp
    const int uh = wid >> 2;         // unit half (0: units 0-25, 1: 26-51)
    const int b  = blockIdx.x * EPB + lane;   // batch element == lane
    const float* xin = input + (size_t)b * SEQN;
    float* outp = out + (size_t)b * SEQN;
    const float bfc = b_fc[0];

    // N-phase unit assignment: u = wid + 8j (j<7, u<51); c state in registers.
    float c[7];
    #pragma unroll
    for (int j = 0; j < 7; j++) c[j] = 0.0f;

    // h packed: h2[i] = (h[2i], h[2i+1]) for i<26; h2[26] = (x, 1.0); h2[27] = 0.
    u64 h2[28];
    #pragma unroll
    for (int i = 0; i < 28; i++) h2[i] = 0;
    float x = __ldg(xin);
    h2[26] = pack2(x, 1.0f);

    for (int t = 0; t < SEQN; t++) {
        // prefetch next x (hidden under G phase)
        float xn = 0.0f;
        if (t + 1 < SEQN) xn = __ldg(xin + t + 1);

        // ---- G phase: this warp's 26 gate rows, all via broadcast weight loads ----
        #pragma unroll 2
        for (int uu = 0; uu < 26; uu++) {
            const int u = uh * 26 + uu;                       // 0..51
            const float4* wr = (const float4*)(Wsh + (g * UP + u) * KP);
            u64 a0 = 0, a1 = 0;
            #pragma unroll
            for (int i = 0; i < 14; i++) {
                float4 w = wr[i];                              // warp-uniform broadcast
                a0 = ffma2(pack2(w.x, w.y), h2[2 * i],     a0);
                a1 = ffma2(pack2(w.z, w.w), h2[2 * i + 1], a1);
            }
            float2 s0 = unpack2(a0), s1 = unpack2(a1);
            gsh[(g * UP + u) * EPB + lane] = (s0.x + s0.y) + (s1.x + s1.y);
        }
        __syncthreads();   // gates visible

        // ---- N phase: units u = wid + 8j; element = lane ----
        #pragma unroll
        for (int j = 0; j < 7; j++) {
            int u = wid + 8 * j;
            if (u < HIDDEN) {
                float gi = gsh[(0 * UP + u) * EPB + lane];
                float gf = gsh[(1 * UP + u) * EPB + lane];
                float gg = gsh[(2 * UP + u) * EPB + lane];
                float go = gsh[(3 * UP + u) * EPB + lane];
                float cn = fsig(gf) * c[j] + fsig(gi) * ftanh(gg);
                c[j] = cn;
                hsh[lane * HSTRIDE + u] = fsig(go) * ftanh(cn);
            }
        }
        __syncthreads();   // h_t visible

        // ---- reload h_t into registers (LDS.64, 8B-aligned, <=2-way conflict) ----
        const u64* hrow = (const u64*)(hsh + lane * HSTRIDE);
        #pragma unroll
        for (int i = 0; i < 26; i++) h2[i] = hrow[i];
        h2[26] = pack2(xn, 1.0f);
        x = xn;

        // ---- y_t = h_t . W_fc + b_fc, by warp 0 ----
        if (wid == 0) {
            const u64* w2 = (const u64*)wfcs;
            u64 ya = 0, yb = 0;
            #pragma unroll
            for (int i = 0; i < 26; i += 2) {
                ya = ffma2(w2[i],     h2[i],     ya);
                yb = ffma2(w2[i + 1], h2[i + 1], yb);
            }
            float2 sa = unpack2(ya), sb = unpack2(yb);
            outp[t] = (sa.x + sa.y) + (sb.x + sb.y) + bfc;
        }
    }
}

extern "C" void kernel_launch(void* const* d_in, const int* in_sizes, int n_in,
                              void* d_out, int out_size)
{
    const float* input = (const float*)d_in[0];
    const float* W_ih  = (const float*)d_in[1];
    const float* W_hh  = (const float*)d_in[2];
    const float* b_ih  = (const float*)d_in[3];
    const float* b_hh  = (const float*)d_in[4];
    const float* W_fc  = (const float*)d_in[5];
    const float* b_fc  = (const float*)d_in[6];
    float* outp = (float*)d_out;

    const size_t smem = (size_t)SMEM_F * sizeof(float);
    cudaFuncSetAttribute(lstm_kernel, cudaFuncAttributeMaxDynamicSharedMemorySize, (int)smem);
    lstm_kernel<<<BATCHN / EPB, NTHREADS, smem>>>(input, W_ih, W_hh, b_ih, b_hh,
                                                  W_fc, b_fc, outp);
}